// round 5
// baseline (speedup 1.0000x reference)
#include <cuda_runtime.h>
#include <cstdint>
#include <cstddef>

#define NUM_USERS 10000
#define EMBED_DIM 64
#define BATCH     4096
#define TB        128
#define TU        64
#define SPLITS    9
#define NCHUNKS   ((NUM_USERS + TU - 1) / TU)   // 157

#define BIT_PITCH 136   // 544B row: 16B-aligned, 8-bank shift per d -> conflict-free transposed stores
#define ET_PITCH  72    // 288B row
#define WS_PITCH  68    // 272B row

#define SMEM_TOTAL ((EMBED_DIM*BIT_PITCH + EMBED_DIM*ET_PITCH + TB*WS_PITCH) * 4)  // 88064 B

__device__ int   g_users[BATCH];
__device__ int   g_items[BATCH];
__device__ float g_partials[SPLITS][BATCH];

// ---- packed f32x2 helpers (sm_103a FFMA2 path; ptxas never auto-fuses this) ----
__device__ __forceinline__ unsigned long long pack2(float lo, float hi) {
    unsigned long long r;
    asm("mov.b64 %0, {%1, %2};" : "=l"(r) : "f"(lo), "f"(hi));
    return r;
}
__device__ __forceinline__ void unpack2(unsigned long long v, float& lo, float& hi) {
    asm("mov.b64 {%0, %1}, %2;" : "=f"(lo), "=f"(hi) : "l"(v));
}
__device__ __forceinline__ void fma2(unsigned long long& d, unsigned long long a, unsigned long long b) {
    asm("fma.rn.f32x2 %0, %1, %2, %0;" : "+l"(d) : "l"(a), "l"(b));
}

// ---- kernel 1: detect index dtype (int32 vs int64) and convert to int32 ----
// If int64: every odd 32-bit word (high half) of items is 0 (values < 2^31).
// If int32: odd words are random item indices in [0,100000) -> essentially
// impossible for 256 of them to all be zero.
__global__ void convert_idx_kernel(const void* users_raw, const void* items_raw) {
    __shared__ int s_or;
    int t = threadIdx.x;
    if (t == 0) s_or = 0;
    __syncthreads();
    const unsigned int* iw = (const unsigned int*)items_raw;
    unsigned int v = iw[2 * t + 1];   // word idx <= 511, safe for both layouts
    atomicOr(&s_or, (int)(v != 0u));
    __syncthreads();
    bool is64 = (s_or == 0);
    for (int i = t; i < BATCH; i += 256) {
        if (is64) {
            g_users[i] = (int)((const long long*)users_raw)[i];
            g_items[i] = (int)((const long long*)items_raw)[i];
        } else {
            g_users[i] = ((const int*)users_raw)[i];
            g_items[i] = ((const int*)items_raw)[i];
        }
    }
}

// ---- kernel 2: social term. Block tile: 128 b x 64 u per chunk, all of D=64.
// partials[split][b] = sum over this split's u-chunks of w[users[b],u] * (E[u]·bi[b])
__global__ __launch_bounds__(256, 2)
void social_kernel(const float* __restrict__ user_emb,
                   const float* __restrict__ item_emb,
                   const float* __restrict__ social)
{
    extern __shared__ float smem[];
    float* sBiT = smem;                                  // [64][BIT_PITCH]  biT[d][b]
    float* sET  = smem + EMBED_DIM * BIT_PITCH;          // [64][ET_PITCH]   ET[d][u]
    float* sW   = sET  + EMBED_DIM * ET_PITCH;           // [128][WS_PITCH]  w[b][u]

    const int tid = threadIdx.x;
    const int tx  = tid & 15;     // u-group: covers u = tx*4 .. tx*4+3
    const int ty  = tid >> 4;     // b-group: covers b = ty*8 .. ty*8+7
    const int b0    = blockIdx.x * TB;
    const int split = blockIdx.y;

    // --- load bi tile (gathered item rows), transposed into sBiT[d][b]; once per block ---
    #pragma unroll
    for (int p = 0; p < 8; p++) {
        int k = tid + p * 256;           // 0..2047
        int row = k >> 4;                // 0..127
        int q   = k & 15;                // float4 index along d
        const float4 v = *(const float4*)&item_emb[(size_t)g_items[b0 + row] * EMBED_DIM + q * 4];
        sBiT[(q * 4 + 0) * BIT_PITCH + row] = v.x;
        sBiT[(q * 4 + 1) * BIT_PITCH + row] = v.y;
        sBiT[(q * 4 + 2) * BIT_PITCH + row] = v.z;
        sBiT[(q * 4 + 3) * BIT_PITCH + row] = v.w;
    }

    // W-row base pointers for this thread's 8 gather rows (fixed across chunks)
    const int lrow = tid >> 4;    // 0..15
    const int lq   = tid & 15;    // float4 col index
    const float* wrow[8];
    #pragma unroll
    for (int p = 0; p < 8; p++)
        wrow[p] = social + (size_t)g_users[b0 + lrow + 16 * p] * NUM_USERS;

    float accf[8];
    #pragma unroll
    for (int i = 0; i < 8; i++) accf[i] = 0.f;

    for (int c = split; c < NCHUNKS; c += SPLITS) {
        const int u0 = c * TU;

        // --- stage E chunk transposed: ET[d][u], 64 rows x 16 float4 ---
        #pragma unroll
        for (int p = 0; p < 4; p++) {
            int k = tid + p * 256;       // 0..1023
            int row = k >> 4;            // u within chunk
            int q   = k & 15;
            int u = u0 + row;
            float4 v = make_float4(0.f, 0.f, 0.f, 0.f);
            if (u < NUM_USERS) v = *(const float4*)&user_emb[(size_t)u * EMBED_DIM + q * 4];
            sET[(q * 4 + 0) * ET_PITCH + row] = v.x;
            sET[(q * 4 + 1) * ET_PITCH + row] = v.y;
            sET[(q * 4 + 2) * ET_PITCH + row] = v.z;
            sET[(q * 4 + 3) * ET_PITCH + row] = v.w;
        }
        // --- stage w tile: 128 rows x 16 float4 (coalesced 256B per 16 threads) ---
        #pragma unroll
        for (int p = 0; p < 8; p++) {
            int row = lrow + 16 * p;
            int col = u0 + lq * 4;
            float4 v = make_float4(0.f, 0.f, 0.f, 0.f);
            if (col < NUM_USERS) v = *(const float4*)&wrow[p][col];   // 10000 % 4 == 0: no partial float4
            *(float4*)&sW[row * WS_PITCH + lq * 4] = v;
        }
        __syncthreads();

        // --- T[b][u] = sum_d bi[b][d] * E[u][d], u packed in f32x2 pairs ---
        unsigned long long T0[8], T1[8];
        #pragma unroll
        for (int i = 0; i < 8; i++) { T0[i] = 0ull; T1[i] = 0ull; }

        const float* ep = sET  + tx * 4;
        const float* bp = sBiT + ty * 8;
        #pragma unroll 8
        for (int d = 0; d < EMBED_DIM; d++) {
            float4 e  = *(const float4*)(ep + d * ET_PITCH);
            unsigned long long e01 = pack2(e.x, e.y);
            unsigned long long e23 = pack2(e.z, e.w);
            float4 p0 = *(const float4*)(bp + d * BIT_PITCH);
            float4 p1 = *(const float4*)(bp + d * BIT_PITCH + 4);
            float bb[8] = {p0.x, p0.y, p0.z, p0.w, p1.x, p1.y, p1.z, p1.w};
            #pragma unroll
            for (int i = 0; i < 8; i++) {
                unsigned long long b2 = pack2(bb[i], bb[i]);
                fma2(T0[i], b2, e01);
                fma2(T1[i], b2, e23);
            }
        }

        // --- fold in w: accf[b] += sum_u w[b][u] * T[b][u] ---
        #pragma unroll
        for (int i = 0; i < 8; i++) {
            const float4 w = *(const float4*)&sW[(ty * 8 + i) * WS_PITCH + tx * 4];
            float t0, t1, t2, t3;
            unpack2(T0[i], t0, t1);
            unpack2(T1[i], t2, t3);
            accf[i] += w.x * t0 + w.y * t1 + w.z * t2 + w.w * t3;
        }
        __syncthreads();   // protect sW/sET from next chunk's stores
    }

    // --- cross-tx reduction (16 partial sums per b) via smem, deterministic ---
    float* red = sW;   // reuse; [16][130] floats = 8320 < 8704
    #pragma unroll
    for (int i = 0; i < 8; i++)
        red[tx * 130 + ty * 8 + i] = accf[i];
    __syncthreads();
    if (tid < TB) {
        float s = 0.f;
        #pragma unroll
        for (int x = 0; x < 16; x++) s += red[x * 130 + tid];
        g_partials[split][b0 + tid] = s;
    }
}

// ---- kernel 3: out[b] = bu·bi + sum_split partials ----
__global__ void finalize_kernel(const float* __restrict__ user_emb,
                                const float* __restrict__ item_emb,
                                float* __restrict__ out)
{
    int b = blockIdx.x * blockDim.x + threadIdx.x;
    if (b >= BATCH) return;
    const float4* ue = (const float4*)(user_emb + (size_t)g_users[b] * EMBED_DIM);
    const float4* ie = (const float4*)(item_emb + (size_t)g_items[b] * EMBED_DIM);
    float s = 0.f;
    #pragma unroll
    for (int k = 0; k < 16; k++) {
        float4 a = ue[k], c = ie[k];
        s += a.x * c.x + a.y * c.y + a.z * c.z + a.w * c.w;
    }
    #pragma unroll
    for (int p = 0; p < SPLITS; p++) s += g_partials[p][b];
    out[b] = s;
}

extern "C" void kernel_launch(void* const* d_in, const int* in_sizes, int n_in,
                              void* d_out, int out_size)
{
    const float* user_emb = (const float*)d_in[0];   // [10000, 64]
    const float* item_emb = (const float*)d_in[1];   // [100000, 64]
    const float* social   = (const float*)d_in[2];   // [10000, 10000]
    const void*  users    = d_in[3];                 // [4096] int32 or int64
    const void*  items    = d_in[4];                 // [4096] int32 or int64

    cudaFuncSetAttribute((const void*)social_kernel,
                         cudaFuncAttributeMaxDynamicSharedMemorySize, SMEM_TOTAL);

    convert_idx_kernel<<<1, 256>>>(users, items);

    dim3 grid(BATCH / TB, SPLITS);   // 32 x 9 = 288 blocks
    social_kernel<<<grid, 256, SMEM_TOTAL>>>(user_emb, item_emb, social);

    finalize_kernel<<<(BATCH + 255) / 256, 256>>>(user_emb, item_emb, (float*)d_out);
}

// round 6
// speedup vs baseline: 1.0698x; 1.0698x over previous
#include <cuda_runtime.h>
#include <cstdint>
#include <cstddef>

#define NUM_USERS 10000
#define EMBED_DIM 64
#define BATCH     4096
#define TB        256          // b rows per block tile
#define TK        64           // k (u) per chunk
#define SPLITS    18           // 16 b-tiles * 18 = 288 blocks = one wave @ occ 2
#define NCHUNKS   ((NUM_USERS + TK - 1) / TK)   // 157

#define A_PITCH   68           // floats per sA row (64 + 4 pad); 8*... see bank notes
#define E_PITCH   68

// smem: sA[256][68] + sE[64][68] + users[256] + items[256]
#define SMEM_FLOATS (TB*A_PITCH + TK*E_PITCH)
#define SMEM_TOTAL  (SMEM_FLOATS*4 + TB*4 + TB*4)   // 89088 B

__device__ float g_partials[SPLITS][BATCH];

// ---- packed f32x2 helpers ----
__device__ __forceinline__ unsigned long long pack2(float lo, float hi) {
    unsigned long long r;
    asm("mov.b64 %0, {%1, %2};" : "=l"(r) : "f"(lo), "f"(hi));
    return r;
}
__device__ __forceinline__ void unpack2(unsigned long long v, float& lo, float& hi) {
    asm("mov.b64 {%0, %1}, %2;" : "=f"(lo), "=f"(hi) : "l"(v));
}
__device__ __forceinline__ void fma2(unsigned long long& d, unsigned long long a, unsigned long long b) {
    asm("fma.rn.f32x2 %0, %1, %2, %0;" : "+l"(d) : "l"(a), "l"(b));
}

// Per-block index dtype sniff: int64 iff ALL sampled high words are zero.
// (int32 case: odd words are random item ids < 100000; all-zero is impossible.)
__device__ __forceinline__ int sniff_is64(const void* items_raw, int tid) {
    const unsigned int* iw = (const unsigned int*)items_raw;
    int any = 0;
    if (tid < 256) any = (iw[2 * tid + 1] != 0u);
    return __syncthreads_or(any) == 0;
}
__device__ __forceinline__ int load_idx(const void* raw, int i, int is64) {
    return is64 ? (int)((const long long*)raw)[i] : ((const int*)raw)[i];
}

// ---- social GEMM: M = W[users] @ E, fused epilogue dot with bi ----
__global__ __launch_bounds__(256, 2)
void social_kernel(const float* __restrict__ user_emb,
                   const float* __restrict__ item_emb,
                   const float* __restrict__ social,
                   const void*  __restrict__ users_raw,
                   const void*  __restrict__ items_raw)
{
    extern __shared__ float smem[];
    float* sA = smem;                         // [256][A_PITCH]  gathered W chunk
    float* sE = smem + TB * A_PITCH;          // [64][E_PITCH]   E chunk
    int*   sU = (int*)(sE + TK * E_PITCH);    // [256] user ids
    int*   sI = sU + TB;                      // [256] item ids

    const int tid   = threadIdx.x;
    const int tx    = tid & 7;                // d-group: d = tx*8 .. tx*8+7
    const int ty    = tid >> 3;               // b-group: b_i = ty + 32*i
    const int b0    = blockIdx.x * TB;
    const int split = blockIdx.y;

    const int is64 = sniff_is64(items_raw, tid);
    if (tid < TB) {
        sU[tid] = load_idx(users_raw, b0 + tid, is64);
        sI[tid] = load_idx(items_raw, b0 + tid, is64);
    }
    __syncthreads();

    // accumulators: pairs over d. T[i][j]: lo <-> d=tx*8+2j, hi <-> d=tx*8+2j+1
    unsigned long long T[8][4];
    #pragma unroll
    for (int i = 0; i < 8; i++)
        #pragma unroll
        for (int j = 0; j < 4; j++) T[i][j] = 0ull;

    const int srow = tid >> 4;   // staging: 2 rows per warp, 16 float4 lanes per row
    const int sk4  = tid & 15;

    for (int c = split; c < NCHUNKS; c += SPLITS) {
        const int u0 = c * TK;
        __syncthreads();   // previous compute done before overwrite

        // --- stage gathered W tile: 256 rows x 64 k (coalesced 256B per row) ---
        #pragma unroll
        for (int p = 0; p < 16; p++) {
            int row = p * 16 + srow;
            int col = u0 + sk4 * 4;
            float4 v = make_float4(0.f, 0.f, 0.f, 0.f);
            if (col < NUM_USERS)
                v = *(const float4*)&social[(size_t)sU[row] * NUM_USERS + col];
            *(float4*)&sA[row * A_PITCH + sk4 * 4] = v;
        }
        // --- stage E chunk: 64 rows x 64 d ---
        #pragma unroll
        for (int p = 0; p < 4; p++) {
            int f   = tid + p * 256;     // 0..1023
            int row = f >> 4;
            int q   = f & 15;
            int u   = u0 + row;
            float4 v = make_float4(0.f, 0.f, 0.f, 0.f);
            if (u < NUM_USERS)
                v = *(const float4*)&user_emb[(size_t)u * EMBED_DIM + q * 4];
            *(float4*)&sE[row * E_PITCH + q * 4] = v;
        }
        __syncthreads();

        // --- compute: 64 rank-1 updates ---
        const float* abase = sA + ty * A_PITCH;
        #pragma unroll 4
        for (int k = 0; k < TK; k++) {
            ulonglong2 e01 = *(const ulonglong2*)&sE[k * E_PITCH + tx * 8];     // (d0,d1),(d2,d3)
            ulonglong2 e23 = *(const ulonglong2*)&sE[k * E_PITCH + tx * 8 + 4]; // (d4,d5),(d6,d7)
            #pragma unroll
            for (int i = 0; i < 8; i++) {
                float a = abase[i * (32 * A_PITCH) + k];
                unsigned long long ad = pack2(a, a);
                fma2(T[i][0], ad, e01.x);
                fma2(T[i][1], ad, e01.y);
                fma2(T[i][2], ad, e23.x);
                fma2(T[i][3], ad, e23.y);
            }
        }
    }

    // --- epilogue: val[i] = sum_d M[b_i][d] * bi[b_i][d] over this thread's d-slice ---
    float val[8];
    #pragma unroll
    for (int i = 0; i < 8; i++) {
        const float* bi = item_emb + (size_t)sI[ty + 32 * i] * EMBED_DIM + tx * 8;
        float4 v0 = *(const float4*)bi;
        float4 v1 = *(const float4*)(bi + 4);
        float t0, t1;
        float s = 0.f;
        unpack2(T[i][0], t0, t1); s += t0 * v0.x + t1 * v0.y;
        unpack2(T[i][1], t0, t1); s += t0 * v0.z + t1 * v0.w;
        unpack2(T[i][2], t0, t1); s += t0 * v1.x + t1 * v1.y;
        unpack2(T[i][3], t0, t1); s += t0 * v1.z + t1 * v1.w;
        val[i] = s;
    }
    // reduce across the 8 tx lanes (consecutive lanes in-warp, deterministic butterfly)
    #pragma unroll
    for (int i = 0; i < 8; i++) {
        val[i] += __shfl_xor_sync(0xffffffffu, val[i], 1);
        val[i] += __shfl_xor_sync(0xffffffffu, val[i], 2);
        val[i] += __shfl_xor_sync(0xffffffffu, val[i], 4);
    }
    if (tx == 0) {
        #pragma unroll
        for (int i = 0; i < 8; i++)
            g_partials[split][b0 + ty + 32 * i] = val[i];
    }
}

// ---- finalize: out[b] = bu.bi + sum_split partials ----
__global__ void finalize_kernel(const float* __restrict__ user_emb,
                                const float* __restrict__ item_emb,
                                const void*  __restrict__ users_raw,
                                const void*  __restrict__ items_raw,
                                float* __restrict__ out)
{
    const int tid = threadIdx.x;
    const int b   = blockIdx.x * 256 + tid;
    const int is64 = sniff_is64(items_raw, tid);
    if (b >= BATCH) return;
    const int u = load_idx(users_raw, b, is64);
    const int it = load_idx(items_raw, b, is64);
    const float4* ue = (const float4*)(user_emb + (size_t)u  * EMBED_DIM);
    const float4* ie = (const float4*)(item_emb + (size_t)it * EMBED_DIM);
    float s = 0.f;
    #pragma unroll
    for (int k = 0; k < 16; k++) {
        float4 a = ue[k], c = ie[k];
        s += a.x * c.x + a.y * c.y + a.z * c.z + a.w * c.w;
    }
    #pragma unroll
    for (int p = 0; p < SPLITS; p++) s += g_partials[p][b];
    out[b] = s;
}

extern "C" void kernel_launch(void* const* d_in, const int* in_sizes, int n_in,
                              void* d_out, int out_size)
{
    const float* user_emb = (const float*)d_in[0];   // [10000, 64]
    const float* item_emb = (const float*)d_in[1];   // [100000, 64]
    const float* social   = (const float*)d_in[2];   // [10000, 10000]
    const void*  users    = d_in[3];                 // [4096] int32 or int64
    const void*  items    = d_in[4];                 // [4096] int32 or int64

    cudaFuncSetAttribute((const void*)social_kernel,
                         cudaFuncAttributeMaxDynamicSharedMemorySize, SMEM_TOTAL);

    dim3 grid(BATCH / TB, SPLITS);   // 16 x 18 = 288 blocks, one wave @ occ 2
    social_kernel<<<grid, 256, SMEM_TOTAL>>>(user_emb, item_emb, social, users, items);

    finalize_kernel<<<BATCH / 256, 256>>>(user_emb, item_emb, users, items, (float*)d_out);
}

// round 8
// speedup vs baseline: 1.3835x; 1.2932x over previous
#include <cuda_runtime.h>
#include <cstdint>
#include <cstddef>

#define NUM_USERS 10000
#define EMBED_DIM 64
#define BATCH     4096
#define TM        128            // b rows per CTA
#define CK        64             // u per chunk
#define SPLITS    9
#define NCH       157            // ceil(10000/64)
#define NTILES    (BATCH / TM)   // 32

// smem buffer layout (bf16 tiles, 128B rows, xor-swizzled)
#define OFF_AHI   0              // A hi: 128 rows x 64 bf16 = 16KB
#define OFF_ALO   16384
#define OFF_BHI   32768          // B hi: 64 rows (u) x 64 bf16 = 8KB
#define OFF_BLO   40960
#define BUF_STRIDE 49152
#define DSM_SIZE  (2 * BUF_STRIDE)   // 96KB

__device__ float        g_partials[SPLITS][BATCH];
__device__ unsigned int g_cnt[NTILES];

// ---------------- helpers ----------------
__device__ __forceinline__ uint32_t smem_u32(const void* p) {
    uint32_t a;
    asm("{ .reg .u64 t; cvta.to.shared.u64 t, %1; cvt.u32.u64 %0, t; }" : "=r"(a) : "l"(p));
    return a;
}
__device__ __forceinline__ uint32_t pack_bf2(float a, float b) {
    uint32_t r;
    asm("{\n\t.reg .b16 l, h;\n\t"
        "cvt.rn.bf16.f32 l, %1;\n\t"
        "cvt.rn.bf16.f32 h, %2;\n\t"
        "mov.b32 %0, {l, h};\n\t}"
        : "=r"(r) : "f"(a), "f"(b));
    return r;
}
__device__ __forceinline__ float bfu_lo(uint32_t p) { return __uint_as_float(p << 16); }
__device__ __forceinline__ float bfu_hi(uint32_t p) { return __uint_as_float(p & 0xFFFF0000u); }

__device__ __forceinline__ void sts8(uint32_t a, uint32_t x, uint32_t y) {
    asm volatile("st.shared.v2.b32 [%0], {%1, %2};" :: "r"(a), "r"(x), "r"(y));
}
__device__ __forceinline__ void sts16(uint32_t a, uint32_t x, uint32_t y, uint32_t z, uint32_t w) {
    asm volatile("st.shared.v4.b32 [%0], {%1, %2, %3, %4};" :: "r"(a), "r"(x), "r"(y), "r"(z), "r"(w));
}
__device__ __forceinline__ void ldsm_x4(uint32_t* r, uint32_t a) {
    asm volatile("ldmatrix.sync.aligned.m8n8.x4.shared.b16 {%0,%1,%2,%3}, [%4];"
        : "=r"(r[0]), "=r"(r[1]), "=r"(r[2]), "=r"(r[3]) : "r"(a));
}
__device__ __forceinline__ void ldsm_x4t(uint32_t* r, uint32_t a) {
    asm volatile("ldmatrix.sync.aligned.m8n8.x4.trans.shared.b16 {%0,%1,%2,%3}, [%4];"
        : "=r"(r[0]), "=r"(r[1]), "=r"(r[2]), "=r"(r[3]) : "r"(a));
}
__device__ __forceinline__ void mma16816(float4& c, const uint32_t* a, uint32_t b0, uint32_t b1) {
    asm volatile(
        "mma.sync.aligned.m16n8k16.row.col.f32.bf16.bf16.f32 "
        "{%0,%1,%2,%3}, {%4,%5,%6,%7}, {%8,%9}, {%0,%1,%2,%3};"
        : "+f"(c.x), "+f"(c.y), "+f"(c.z), "+f"(c.w)
        : "r"(a[0]), "r"(a[1]), "r"(a[2]), "r"(a[3]), "r"(b0), "r"(b1));
}

// Index dtype sniff: int64 iff all sampled high words are zero.
__device__ __forceinline__ int sniff_is64(const void* items_raw, int tid) {
    const unsigned int* iw = (const unsigned int*)items_raw;
    int any = (tid < 256) ? (iw[2 * tid + 1] != 0u) : 0;
    return __syncthreads_or(any) == 0;
}
__device__ __forceinline__ int load_idx(const void* raw, int i, int is64) {
    return is64 ? (int)((const long long*)raw)[i] : ((const int*)raw)[i];
}

// ---------------- fused kernel ----------------
__global__ __launch_bounds__(256, 2)
void bpr_kernel(const float* __restrict__ user_emb,
                const float* __restrict__ item_emb,
                const float* __restrict__ social,
                const void*  __restrict__ users_raw,
                const void*  __restrict__ items_raw,
                float* __restrict__ out)
{
    extern __shared__ __align__(16) char dsm[];
    __shared__ int sU[TM];
    __shared__ int sI[TM];
    __shared__ unsigned int s_old;

    const uint32_t sb  = smem_u32(dsm);
    const int tid  = threadIdx.x;
    const int wid  = tid >> 5;
    const int lane = tid & 31;
    const int b0    = blockIdx.x * TM;
    const int split = blockIdx.y;

    const int is64 = sniff_is64(items_raw, tid);
    if (tid < TM) {
        sU[tid] = load_idx(users_raw, b0 + tid, is64);
        sI[tid] = load_idx(items_raw, b0 + tid, is64);
    }
    __syncthreads();

    // ---- staging geometry ----
    const int arow  = tid >> 1;          // 0..127: A row (b)
    const int ahalf = tid & 1;           // which 32-u half
    const float* wrow = social + (size_t)sU[arow] * NUM_USERS;
    const uint32_t aStOff = (uint32_t)(arow * 128) + (uint32_t)(((ahalf * 64)) ^ ((arow & 7) << 4));
    // note: swizzle xor only touches bits 4-6; ahalf*64+j*16 < 128, handled per j below

    // ---- ldmatrix geometry (per lane) ----
    const int asub = lane >> 3, ar = lane & 7;
    const int aRow = wid * 16 + (asub & 1) * 8 + ar;
    const uint32_t aKpart = (uint32_t)((asub >> 1) * 16);
    const uint32_t aXor   = (uint32_t)((aRow & 7) << 4);
    const uint32_t aRowB  = (uint32_t)(aRow * 128);

    const int bm = lane >> 3, br = lane & 7;
    const uint32_t bRowByte = (uint32_t)(((bm & 1) * 8 + br) * 128);
    const int      bJoff    = bm >> 1;
    const uint32_t bXor     = (uint32_t)(br << 4);

    float4 acc[8];
    #pragma unroll
    for (int n = 0; n < 8; n++) acc[n] = make_float4(0.f, 0.f, 0.f, 0.f);

    // ---- stage first chunk into buf 0 ----
    {
        const int u0 = split * CK;
        uint32_t Ah = sb + OFF_AHI, Al = sb + OFF_ALO, Bh = sb + OFF_BHI, Bl = sb + OFF_BLO;
        #pragma unroll
        for (int j = 0; j < 4; j++) {
            int col = u0 + ahalf * 32 + j * 8;
            float4 a = (col     < NUM_USERS) ? *(const float4*)(wrow + col)     : make_float4(0,0,0,0);
            float4 b = (col + 4 < NUM_USERS) ? *(const float4*)(wrow + col + 4) : make_float4(0,0,0,0);
            uint32_t h0 = pack_bf2(a.x, a.y), h1 = pack_bf2(a.z, a.w);
            uint32_t h2 = pack_bf2(b.x, b.y), h3 = pack_bf2(b.z, b.w);
            uint32_t l0 = pack_bf2(a.x - bfu_lo(h0), a.y - bfu_hi(h0));
            uint32_t l1 = pack_bf2(a.z - bfu_lo(h1), a.w - bfu_hi(h1));
            uint32_t l2 = pack_bf2(b.x - bfu_lo(h2), b.y - bfu_hi(h2));
            uint32_t l3 = pack_bf2(b.z - bfu_lo(h3), b.w - bfu_hi(h3));
            uint32_t off = (uint32_t)(arow * 128) + (uint32_t)(((ahalf * 64 + j * 16)) ^ ((arow & 7) << 4));
            sts16(Ah + off, h0, h1, h2, h3);
            sts16(Al + off, l0, l1, l2, l3);
        }
        #pragma unroll
        for (int i = 0; i < 4; i++) {
            int idx = tid + i * 256;
            int row = idx >> 4, q = idx & 15;
            int u = u0 + row;
            float4 v = (u < NUM_USERS) ? *(const float4*)&user_emb[(size_t)u * EMBED_DIM + q * 4]
                                       : make_float4(0,0,0,0);
            uint32_t h0 = pack_bf2(v.x, v.y), h1 = pack_bf2(v.z, v.w);
            uint32_t l0 = pack_bf2(v.x - bfu_lo(h0), v.y - bfu_hi(h0));
            uint32_t l1 = pack_bf2(v.z - bfu_lo(h1), v.w - bfu_hi(h1));
            uint32_t off = (uint32_t)(row * 128) + (uint32_t)((q * 8) ^ ((row & 7) << 4));
            sts8(Bh + off, h0, h1);
            sts8(Bl + off, l0, l1);
        }
    }
    __syncthreads();

    // ---- mainloop: compute chunk c while prefetching c+SPLITS ----
    int buf = 0;
    for (int c = split; c < NCH; c += SPLITS) {
        const int cn = c + SPLITS;
        const bool more = (cn < NCH);

        // prefetch next chunk to registers (overlaps compute below)
        float4 wa[8], eb[4];
        if (more) {
            const int u0 = cn * CK;
            #pragma unroll
            for (int j = 0; j < 4; j++) {
                int col = u0 + ahalf * 32 + j * 8;
                wa[2*j]   = (col     < NUM_USERS) ? *(const float4*)(wrow + col)     : make_float4(0,0,0,0);
                wa[2*j+1] = (col + 4 < NUM_USERS) ? *(const float4*)(wrow + col + 4) : make_float4(0,0,0,0);
            }
            #pragma unroll
            for (int i = 0; i < 4; i++) {
                int idx = tid + i * 256;
                int row = idx >> 4, q = idx & 15;
                int u = u0 + row;
                eb[i] = (u < NUM_USERS) ? *(const float4*)&user_emb[(size_t)u * EMBED_DIM + q * 4]
                                        : make_float4(0,0,0,0);
            }
        }

        // compute on current buffer
        {
            const uint32_t bo = sb + (buf ? BUF_STRIDE : 0);
            const uint32_t AhB = bo + OFF_AHI + aRowB;
            const uint32_t AlB = bo + OFF_ALO + aRowB;
            const uint32_t BhB = bo + OFF_BHI + bRowByte;
            const uint32_t BlB = bo + OFF_BLO + bRowByte;
            #pragma unroll
            for (int ks = 0; ks < 4; ks++) {
                uint32_t aH[4], aL[4];
                const uint32_t ka = (uint32_t)((ks * 32 + aKpart)) ^ aXor;
                ldsm_x4(aH, AhB + ka);
                ldsm_x4(aL, AlB + ka);
                const uint32_t kb = (uint32_t)(ks * 2048);
                #pragma unroll
                for (int j = 0; j < 8; j += 2) {
                    uint32_t bH[4], bL[4];
                    const uint32_t colsw = (uint32_t)(((j + bJoff) * 16)) ^ bXor;
                    ldsm_x4t(bH, BhB + kb + colsw);
                    ldsm_x4t(bL, BlB + kb + colsw);
                    mma16816(acc[j],   aH, bH[0], bH[1]);
                    mma16816(acc[j],   aH, bL[0], bL[1]);
                    mma16816(acc[j],   aL, bH[0], bH[1]);
                    mma16816(acc[j+1], aH, bH[2], bH[3]);
                    mma16816(acc[j+1], aH, bL[2], bL[3]);
                    mma16816(acc[j+1], aL, bH[2], bH[3]);
                }
            }
        }

        // store prefetched chunk into the other buffer
        if (more) {
            const uint32_t bo = sb + (buf ? 0 : BUF_STRIDE);
            const uint32_t Ah = bo + OFF_AHI, Al = bo + OFF_ALO;
            const uint32_t Bh = bo + OFF_BHI, Bl = bo + OFF_BLO;
            #pragma unroll
            for (int j = 0; j < 4; j++) {
                float4 a = wa[2*j], b = wa[2*j+1];
                uint32_t h0 = pack_bf2(a.x, a.y), h1 = pack_bf2(a.z, a.w);
                uint32_t h2 = pack_bf2(b.x, b.y), h3 = pack_bf2(b.z, b.w);
                uint32_t l0 = pack_bf2(a.x - bfu_lo(h0), a.y - bfu_hi(h0));
                uint32_t l1 = pack_bf2(a.z - bfu_lo(h1), a.w - bfu_hi(h1));
                uint32_t l2 = pack_bf2(b.x - bfu_lo(h2), b.y - bfu_hi(h2));
                uint32_t l3 = pack_bf2(b.z - bfu_lo(h3), b.w - bfu_hi(h3));
                uint32_t off = (uint32_t)(arow * 128) + (uint32_t)(((ahalf * 64 + j * 16)) ^ ((arow & 7) << 4));
                sts16(Ah + off, h0, h1, h2, h3);
                sts16(Al + off, l0, l1, l2, l3);
            }
            #pragma unroll
            for (int i = 0; i < 4; i++) {
                int idx = tid + i * 256;
                int row = idx >> 4, q = idx & 15;
                float4 v = eb[i];
                uint32_t h0 = pack_bf2(v.x, v.y), h1 = pack_bf2(v.z, v.w);
                uint32_t l0 = pack_bf2(v.x - bfu_lo(h0), v.y - bfu_hi(h0));
                uint32_t l1 = pack_bf2(v.z - bfu_lo(h1), v.w - bfu_hi(h1));
                uint32_t off = (uint32_t)(row * 128) + (uint32_t)((q * 8) ^ ((row & 7) << 4));
                sts8(Bh + off, h0, h1);
                sts8(Bl + off, l0, l1);
            }
        }
        __syncthreads();
        buf ^= 1;
    }

    // ---- epilogue: dot with bi, reduce across the 4 lanes per row ----
    {
        const int r0 = wid * 16 + (lane >> 2);
        const int r1 = r0 + 8;
        const float* ip0 = item_emb + (size_t)sI[r0] * EMBED_DIM;
        const float* ip1 = item_emb + (size_t)sI[r1] * EMBED_DIM;
        const int cbase = (lane & 3) * 2;
        float v0 = 0.f, v1 = 0.f;
        #pragma unroll
        for (int n = 0; n < 8; n++) {
            const int cn = n * 8 + cbase;
            float2 e0 = *(const float2*)(ip0 + cn);
            float2 e1 = *(const float2*)(ip1 + cn);
            v0 += acc[n].x * e0.x + acc[n].y * e0.y;
            v1 += acc[n].z * e1.x + acc[n].w * e1.y;
        }
        v0 += __shfl_xor_sync(0xffffffffu, v0, 1);
        v0 += __shfl_xor_sync(0xffffffffu, v0, 2);
        v1 += __shfl_xor_sync(0xffffffffu, v1, 1);
        v1 += __shfl_xor_sync(0xffffffffu, v1, 2);
        if ((lane & 3) == 0) {
            g_partials[split][b0 + r0] = v0;
            g_partials[split][b0 + r1] = v1;
        }
    }
    __syncthreads();

    // ---- last split for this b-tile finishes: fixed-order sum + pos term ----
    if (tid == 0) {
        __threadfence();
        s_old = atomicAdd(&g_cnt[blockIdx.x], 1u);
    }
    __syncthreads();
    if (s_old == SPLITS - 1) {
        __threadfence();
        if (tid < TM) {
            const int b = b0 + tid;
            float s = 0.f;
            #pragma unroll
            for (int p = 0; p < SPLITS; p++) s += g_partials[p][b];
            const float4* ue = (const float4*)(user_emb + (size_t)sU[tid] * EMBED_DIM);
            const float4* ie = (const float4*)(item_emb + (size_t)sI[tid] * EMBED_DIM);
            float d = 0.f;
            #pragma unroll
            for (int k = 0; k < 16; k++) {
                float4 a = ue[k], c = ie[k];
                d += a.x * c.x + a.y * c.y + a.z * c.z + a.w * c.w;
            }
            out[b] = s + d;
        }
        __syncthreads();
        if (tid == 0) g_cnt[blockIdx.x] = 0u;   // self-reset for graph replay
    }
}

extern "C" void kernel_launch(void* const* d_in, const int* in_sizes, int n_in,
                              void* d_out, int out_size)
{
    const float* user_emb = (const float*)d_in[0];   // [10000, 64]
    const float* item_emb = (const float*)d_in[1];   // [100000, 64]
    const float* social   = (const float*)d_in[2];   // [10000, 10000]
    const void*  users    = d_in[3];                 // [4096] idx
    const void*  items    = d_in[4];                 // [4096] idx

    cudaFuncSetAttribute((const void*)bpr_kernel,
                         cudaFuncAttributeMaxDynamicSharedMemorySize, DSM_SIZE);

    dim3 grid(NTILES, SPLITS);   // 32 x 9 = 288 CTAs
    bpr_kernel<<<grid, 256, DSM_SIZE>>>(user_emb, item_emb, social, users, items, (float*)d_out);
}